// round 7
// baseline (speedup 1.0000x reference)
#include <cuda_runtime.h>
#include <cstdint>

#define BB 2
#define MM 4
#define CCH 64
#define VV 110592
#define KK 4
#define CB 8               // channels per block
#define CG 8               // channel groups
#define VS 24              // V splits
#define VCHUNK (VV/VS)     // 4608 elems
#define SELEM 512          // elems per stage
#define NST (VCHUNK/SELEM) // 9 stages
#define NSTAGE 4           // ring slots
#define NBLK (BB*MM*CG*VS) // 1536
#define THREADS 256
#define NWARP 8
#define EPSL 1e-6f

// per-stage smem layout (bytes)
#define W_OFFB 16384       // f: 8ch * 2048
#define T_OFFB 18432       // w: 2048
#define STAGE_B 22528      // t: worst-case int64 4096
#define DYN_BYTES (NSTAGE*STAGE_B)   // 90112

// ---- scratch (no allocations allowed) ----
__device__ float g_numpart[NBLK * 32];
__device__ float g_twpart[BB*MM*VS*KK];
__device__ float g_cntpart[BB*VS*KK];
__device__ unsigned g_ctr;              // zero-init; reset each launch

extern __shared__ char dynsm[];

#define BULK(dst, src, nbytes, mbar) \
    asm volatile("cp.async.bulk.shared::cluster.global.mbarrier::complete_tx::bytes [%0], [%1], %2, [%3];" \
                 :: "r"(dst), "l"(src), "r"(nbytes), "r"(mbar) : "memory")
#define MB_INIT(mbar, cnt) \
    asm volatile("mbarrier.init.shared.b64 [%0], %1;" :: "r"(mbar), "r"(cnt) : "memory")
#define MB_EXPECT_TX(mbar, tx) \
    asm volatile("mbarrier.arrive.expect_tx.shared.b64 _, [%0], %1;" :: "r"(mbar), "r"(tx) : "memory")
#define MB_ARRIVE(mbar) \
    asm volatile("mbarrier.arrive.shared.b64 _, [%0];" :: "r"(mbar) : "memory")

__device__ __forceinline__ void mb_wait_acq(uint32_t mbar, uint32_t parity) {
    uint32_t done = 0;
    while (!done) {
        asm volatile(
            "{\n\t.reg .pred p;\n\t"
            "mbarrier.try_wait.parity.acquire.cta.shared::cta.b64 p, [%1], %2, 0x989680;\n\t"
            "selp.b32 %0, 1, 0, p;\n\t}"
            : "=r"(done) : "r"(mbar), "r"(parity) : "memory");
    }
}
__device__ __forceinline__ void mb_wait_rlx(uint32_t mbar, uint32_t parity) {
    uint32_t done = 0;
    while (!done) {
        asm volatile(
            "{\n\t.reg .pred p;\n\t"
            "mbarrier.try_wait.parity.relaxed.cta.shared::cta.b64 p, [%1], %2, 0x989680;\n\t"
            "selp.b32 %0, 1, 0, p;\n\t}"
            : "=r"(done) : "r"(mbar), "r"(parity) : "memory");
    }
}

__global__ __launch_bounds__(THREADS, 2) void kmain(const float* __restrict__ f,
                                                    const float* __restrict__ w,
                                                    const int*   __restrict__ tw_words,
                                                    float* __restrict__ out) {
    const int bm = blockIdx.x;   // 0..7 (b*4+m)
    const int cg = blockIdx.y;   // 0..7
    const int vs = blockIdx.z;   // 0..23
    const int b  = bm >> 2;
    const int tid = threadIdx.x;
    const int lane = tid & 31, wid = tid >> 5;

    __shared__ float sred[NWARP][32];
    __shared__ float s_proto[2048];
    __shared__ float s_tw[32];
    __shared__ float s_cnt[8];
    __shared__ float s_aterm[48], s_acnt[48], s_sterm[48], s_scnt[48];
    __shared__ int   s_last;
    __shared__ __align__(8) unsigned long long mbars[2*NSTAGE];  // full[0..3], empty[4..7]

    // ---- dtype detect: one high-word per thread ----
    const int is64 = (__syncthreads_or(tw_words[2*tid + 1]) == 0);
    const uint32_t TXB = 18432u + (is64 ? 4096u : 2048u);

    const uint32_t mb0 = (uint32_t)__cvta_generic_to_shared(mbars);
#define FULLB(i)  (mb0 + (i)*8)
#define EMPTYB(i) (mb0 + 32 + (i)*8)

    if (tid == 0) {
#pragma unroll
        for (int i = 0; i < NSTAGE; i++) { MB_INIT(FULLB(i), 1); MB_INIT(EMPTYB(i), NWARP); }
    }
    __syncthreads();

    const long vbase = (long)vs * VCHUNK;
    const char* fsrcB  = (const char*)(f + ((long)bm*CCH + (long)cg*CB)*VV + vbase);
    const char* wsrcB  = (const char*)(w + (long)bm*VV + vbase);
    const char* tsrcB  = (const char*)tw_words + ((long)b*VV + vbase) * (is64 ? 8 : 4);
    const int   tstride = is64 ? 4096 : 2048;

    const uint32_t sm0 = (uint32_t)__cvta_generic_to_shared(dynsm);

#define ISSUE(j) do {                                                     \
        const uint32_t sb_ = sm0 + ((j) & 3)*STAGE_B;                     \
        MB_EXPECT_TX(FULLB((j) & 3), TXB);                                \
        _Pragma("unroll")                                                 \
        for (int cc_ = 0; cc_ < CB; cc_++)                                \
            BULK(sb_ + cc_*2048, fsrcB + (long)(j)*2048 + (long)cc_*(VV*4), 2048, FULLB((j)&3)); \
        BULK(sb_ + W_OFFB, wsrcB + (long)(j)*2048, 2048, FULLB((j)&3));   \
        BULK(sb_ + T_OFFB, tsrcB + (long)(j)*tstride, tstride, FULLB((j)&3)); \
    } while (0)

    float acc[CB][KK];
#pragma unroll
    for (int cc = 0; cc < CB; cc++)
#pragma unroll
        for (int k = 0; k < KK; k++) acc[cc][k] = 0.f;
    float twl[KK] = {0.f,0.f,0.f,0.f};
    float cl [KK] = {0.f,0.f,0.f,0.f};
    const bool doTW  = (cg == 0);
    const bool doCNT = doTW && ((bm & 3) == 0);

    if (tid == 0) { ISSUE(0); ISSUE(1); ISSUE(2); }

#pragma unroll 1
    for (int s = 0; s < NST; s++) {
        // producer: keep 3 stages in flight
        if (tid == 0 && s + 3 < NST) {
            const int j = s + 3;
            if (j >= NSTAGE) mb_wait_rlx(EMPTYB(j & 3), ((j >> 2) - 1) & 1);
            ISSUE(j);
        }
        mb_wait_acq(FULLB(s & 3), (s >> 2) & 1);

        const char* sb = dynsm + (s & 3)*STAGE_B;
        float2 wv = *(const float2*)(sb + W_OFFB + tid*8);
        int t0, t1;
        if (is64) {
            int4 q = *(const int4*)(sb + T_OFFB + tid*16);
            t0 = q.x; t1 = q.z;
        } else {
            int2 q = *(const int2*)(sb + T_OFFB + tid*8);
            t0 = q.x; t1 = q.y;
        }

        float msk0[KK], msk1[KK];
#pragma unroll
        for (int k = 0; k < KK; k++) {
            msk0[k] = (t0 == k) ? wv.x : 0.f;
            msk1[k] = (t1 == k) ? wv.y : 0.f;
        }
        if (doTW) {
#pragma unroll
            for (int k = 0; k < KK; k++) twl[k] += msk0[k] + msk1[k];
        }
        if (doCNT) {
#pragma unroll
            for (int k = 0; k < KK; k++)
                cl[k] += ((t0==k)?1.f:0.f) + ((t1==k)?1.f:0.f);
        }
#pragma unroll
        for (int cc = 0; cc < CB; cc++) {
            float2 fv = *(const float2*)(sb + cc*2048 + tid*8);
#pragma unroll
            for (int k = 0; k < KK; k++) {
                acc[cc][k] += fv.x * msk0[k];
                acc[cc][k] += fv.y * msk1[k];
            }
        }
        if (lane == 0) MB_ARRIVE(EMPTYB(s & 3));
    }

    // ---- block-reduce 32 accumulators over 8 warps ----
#pragma unroll
    for (int cc = 0; cc < CB; cc++)
#pragma unroll
        for (int k = 0; k < KK; k++)
#pragma unroll
            for (int off = 16; off > 0; off >>= 1)
                acc[cc][k] += __shfl_down_sync(0xffffffffu, acc[cc][k], off);
    if (lane == 0) {
#pragma unroll
        for (int cc = 0; cc < CB; cc++)
#pragma unroll
            for (int k = 0; k < KK; k++) sred[wid][cc*KK + k] = acc[cc][k];
    }
    __syncthreads();
    const int bid = (bm*CG + cg)*VS + vs;
    if (tid < 32) {
        float s = 0.f;
#pragma unroll
        for (int ww = 0; ww < NWARP; ww++) s += sred[ww][tid];
        g_numpart[bid*32 + tid] = s;
    }
    __syncthreads();

    // ---- block-reduce tw/cnt ----
    {
        float vals[8];
#pragma unroll
        for (int j = 0; j < 4; j++) { vals[j] = twl[j]; vals[4+j] = cl[j]; }
#pragma unroll
        for (int j = 0; j < 8; j++)
#pragma unroll
            for (int off = 16; off > 0; off >>= 1)
                vals[j] += __shfl_down_sync(0xffffffffu, vals[j], off);
        if (lane == 0) {
#pragma unroll
            for (int j = 0; j < 8; j++) sred[wid][j] = vals[j];
        }
        __syncthreads();
        if (tid < 8) {
            float s = 0.f;
#pragma unroll
            for (int ww = 0; ww < NWARP; ww++) s += sred[ww][tid];
            if (tid < 4) {
                if (doTW) g_twpart[(bm*VS + vs)*4 + tid] = s;
            } else {
                if (doCNT) g_cntpart[(b*VS + vs)*4 + (tid-4)] = s;
            }
        }
    }

    // ---- last-block-done finalize ----
    __threadfence();
    __syncthreads();
    if (tid == 0) {
        unsigned old = atomicAdd(&g_ctr, 1u);
        s_last = (old == (unsigned)(NBLK - 1));
    }
    __syncthreads();
    if (!s_last) return;

    // Phase A: tw (32) + cnt (8)
    if (tid < 32) {
        int bm_ = tid >> 2, k = tid & 3;
        float s = 0.f;
        for (int v = 0; v < VS; v++) s += g_twpart[(bm_*VS + v)*4 + k];
        s_tw[tid] = s + EPSL;
    } else if (tid < 40) {
        int j = tid - 32, b_ = j >> 2, k = j & 3;
        float s = 0.f;
        for (int v = 0; v < VS; v++) s += g_cntpart[(b_*VS + v)*4 + k];
        s_cnt[j] = s;
    }
    __syncthreads();

    // Phase B: proto raw = num / tw
    for (int cell = tid; cell < 2048; cell += THREADS) {
        int bm_ = cell >> 8;
        int rem = cell & 255;
        int c = rem >> 2, k = rem & 3;
        int cg_ = c >> 3, cc = c & 7;
        float s = 0.f;
        for (int v = 0; v < VS; v++)
            s += g_numpart[((bm_*CG + cg_)*VS + v)*32 + cc*4 + k];
        s_proto[(bm_*4 + k)*64 + c] = s / s_tw[bm_*4 + k];
    }
    __syncthreads();

    // Phase C: normalize 32 rows (8 warps x 4 rows)
#pragma unroll
    for (int j = 0; j < 4; j++) {
        int r = wid + NWARP*j;
        float v1 = s_proto[r*64 + lane];
        float v2 = s_proto[r*64 + lane + 32];
        float ss = v1*v1 + v2*v2;
#pragma unroll
        for (int off = 16; off > 0; off >>= 1)
            ss += __shfl_xor_sync(0xffffffffu, ss, off);
        float norm = fmaxf(sqrtf(fmaxf(ss, 1e-24f)), 1e-12f);
        float inv = 1.f / norm;
        s_proto[r*64 + lane]      = v1 * inv;
        s_proto[r*64 + lane + 32] = v2 * inv;
    }
    __syncthreads();

    // Phase D: 96 pair dot products (8 warps x 12 pairs)
    {
        const int p1t[6] = {0,0,0,1,1,2};
        const int p2t[6] = {1,2,3,2,3,3};
        for (int p = wid; p < 96; p += NWARP) {
            int r1, r2, outidx;
            bool val;
            bool isAlign = (p < 48);
            float om = 1.f;
            if (isAlign) {
                int pa = p;
                int b_ = pa / 24; int rem = pa % 24;
                int mp = rem >> 2, k = rem & 3;
                int m = p1t[mp], n = p2t[mp];
                r1 = (b_*4 + m)*4 + k;
                r2 = (b_*4 + n)*4 + k;
                val = (s_cnt[b_*4 + k] >= 1.f) && (k != 0);
                float cd = s_cnt[b_*4 + k] + EPSL;
                om = (s_tw[r1] / cd) * (s_tw[r2] / cd);
                outidx = pa;
            } else {
                int ps = p - 48;
                int b_ = ps / 24; int rem = ps % 24;
                int m = rem / 6, kp = rem % 6;
                int k1 = p1t[kp], k2 = p2t[kp];
                r1 = (b_*4 + m)*4 + k1;
                r2 = (b_*4 + m)*4 + k2;
                val = (s_cnt[b_*4 + k1] >= 1.f) && (k1 != 0) &&
                      (s_cnt[b_*4 + k2] >= 1.f) && (k2 != 0);
                outidx = ps;
            }
            float a1 = s_proto[r1*64 + lane],      b1 = s_proto[r2*64 + lane];
            float a2 = s_proto[r1*64 + lane + 32], b2 = s_proto[r2*64 + lane + 32];
            float dot = a1*b1 + a2*b2;
#pragma unroll
            for (int off = 16; off > 0; off >>= 1)
                dot += __shfl_xor_sync(0xffffffffu, dot, off);
            if (lane == 0) {
                if (isAlign) {
                    s_aterm[outidx] = val ? om * fmaxf(0.9f - dot, 0.f) : 0.f;
                    s_acnt[outidx]  = val ? 1.f : 0.f;
                } else {
                    s_sterm[outidx] = val ? fmaxf(dot - 0.1f, 0.f) : 0.f;
                    s_scnt[outidx]  = val ? 1.f : 0.f;
                }
            }
        }
    }
    __syncthreads();

    // Phase E: scalar loss + counter reset
    if (tid == 0) {
        float as = 0.f, ac = 0.f, ssum = 0.f, sc = 0.f;
        for (int i = 0; i < 48; i++) { as += s_aterm[i]; ac += s_acnt[i]; }
        for (int i = 0; i < 48; i++) { ssum += s_sterm[i]; sc += s_scnt[i]; }
        out[0] = as / (ac + EPSL) + ssum / (sc + EPSL);
        g_ctr = 0;
    }
}

extern "C" void kernel_launch(void* const* d_in, const int* in_sizes, int n_in,
                              void* d_out, int out_size) {
    const float* feats   = (const float*)d_in[0];
    const float* weights = (const float*)d_in[1];
    const int*   tgt_w   = (const int*)d_in[2];   // int32 or int64; detected on-device
    float* out = (float*)d_out;

    cudaFuncSetAttribute(kmain, cudaFuncAttributeMaxDynamicSharedMemorySize, DYN_BYTES);
    kmain<<<dim3(BB*MM, CG, VS), THREADS, DYN_BYTES>>>(feats, weights, tgt_w, out);
}

// round 9
// speedup vs baseline: 1.1703x; 1.1703x over previous
#include <cuda_runtime.h>
#include <cstdint>

#define BB 2
#define MM 4
#define CCH 64
#define VV 110592
#define KK 4
#define CB 8               // channels per block
#define CG 8               // channel groups
#define VS 6               // V splits
#define VCHUNK (VV/VS)     // 18432 elems
#define SELEM 2048         // elems per stage
#define NST (VCHUNK/SELEM) // 9 stages
#define NSTAGE 3           // ring slots
#define NBLK (BB*MM*CG*VS) // 384
#define THREADS 512
#define NWARP 16
#define EPSL 1e-6f

// f-only stages: 8 ch * 8192 B
#define STAGE_B 65536
#define DYN_BYTES (NSTAGE*STAGE_B)   // 196608

// ---- scratch (no allocations allowed) ----
__device__ float g_numpart[NBLK * 32];
__device__ float g_twpart[BB*MM*VS*KK];
__device__ float g_cntpart[BB*VS*KK];
__device__ unsigned g_ctr;              // zero-init; reset each launch

extern __shared__ char dynsm[];

#define BULK(dst, src, nbytes, mbar) \
    asm volatile("cp.async.bulk.shared::cluster.global.mbarrier::complete_tx::bytes [%0], [%1], %2, [%3];" \
                 :: "r"(dst), "l"(src), "r"(nbytes), "r"(mbar) : "memory")
#define MB_INIT(mbar, cnt) \
    asm volatile("mbarrier.init.shared.b64 [%0], %1;" :: "r"(mbar), "r"(cnt) : "memory")
#define MB_EXPECT_TX(mbar, tx) \
    asm volatile("mbarrier.arrive.expect_tx.shared.b64 _, [%0], %1;" :: "r"(mbar), "r"(tx) : "memory")
#define MB_ARRIVE(mbar) \
    asm volatile("mbarrier.arrive.shared.b64 _, [%0];" :: "r"(mbar) : "memory")

__device__ __forceinline__ void mb_wait_acq(uint32_t mbar, uint32_t parity) {
    uint32_t done = 0;
    while (!done) {
        asm volatile(
            "{\n\t.reg .pred p;\n\t"
            "mbarrier.try_wait.parity.acquire.cta.shared::cta.b64 p, [%1], %2, 0x989680;\n\t"
            "selp.b32 %0, 1, 0, p;\n\t}"
            : "=r"(done) : "r"(mbar), "r"(parity) : "memory");
    }
}
__device__ __forceinline__ void mb_wait_rlx(uint32_t mbar, uint32_t parity) {
    uint32_t done = 0;
    while (!done) {
        asm volatile(
            "{\n\t.reg .pred p;\n\t"
            "mbarrier.try_wait.parity.relaxed.cta.shared::cta.b64 p, [%1], %2, 0x989680;\n\t"
            "selp.b32 %0, 1, 0, p;\n\t}"
            : "=r"(done) : "r"(mbar), "r"(parity) : "memory");
    }
}

__global__ __launch_bounds__(THREADS, 1) void kmain(const float* __restrict__ f,
                                                    const float* __restrict__ w,
                                                    const int*   __restrict__ tw_words,
                                                    float* __restrict__ out) {
    const int bm = blockIdx.x;   // 0..7 (b*4+m)
    const int cg = blockIdx.y;   // 0..7
    const int vs = blockIdx.z;   // 0..5
    const int b  = bm >> 2;
    const int tid = threadIdx.x;
    const int lane = tid & 31, wid = tid >> 5;

    __shared__ float sred[NWARP][32];
    __shared__ float s_proto[2048];
    __shared__ float s_tw[32];
    __shared__ float s_cnt[8];
    __shared__ float s_aterm[48], s_acnt[48], s_sterm[48], s_scnt[48];
    __shared__ int   s_last;
    __shared__ __align__(8) unsigned long long mbars[2*NSTAGE];

    // ---- dtype detect: one high-word per thread ----
    const int is64 = (__syncthreads_or(tw_words[2*tid + 1]) == 0);

    const uint32_t mb0 = (uint32_t)__cvta_generic_to_shared(mbars);
#define FULLB(i)  (mb0 + (i)*8)
#define EMPTYB(i) (mb0 + 24 + (i)*8)

    if (tid == 0) {
#pragma unroll
        for (int i = 0; i < NSTAGE; i++) { MB_INIT(FULLB(i), 1); MB_INIT(EMPTYB(i), NWARP); }
    }
    __syncthreads();

    const long vbase = (long)vs * VCHUNK;
    const char*  fsrcB = (const char*)(f + ((long)bm*CCH + (long)cg*CB)*VV + vbase);
    const float* wsrc  = w + (long)bm*VV + vbase + tid*4;   // one float4/thread/stage
    // per-stage int4 strides: is32 -> 512 int4 per stage; is64 -> 1024 int4 per stage
    const int4*  t32   = (const int4*)((const char*)tw_words + ((long)b*VV + vbase)*4) + tid;
    const int4*  t64   = (const int4*)((const char*)tw_words + ((long)b*VV + vbase)*8) + tid*2;

    const uint32_t sm0 = (uint32_t)__cvta_generic_to_shared(dynsm);

#define ISSUE(j, slot) do {                                               \
        const uint32_t sb_ = sm0 + (slot)*STAGE_B;                        \
        MB_EXPECT_TX(FULLB(slot), STAGE_B);                               \
        _Pragma("unroll")                                                 \
        for (int cc_ = 0; cc_ < CB; cc_++)                                \
            BULK(sb_ + cc_*8192, fsrcB + (long)(j)*8192 + (long)cc_*(VV*4), 8192, FULLB(slot)); \
    } while (0)

    float acc[CB][KK];
#pragma unroll
    for (int cc = 0; cc < CB; cc++)
#pragma unroll
        for (int k = 0; k < KK; k++) acc[cc][k] = 0.f;
    float twl[KK] = {0.f,0.f,0.f,0.f};
    float cl [KK] = {0.f,0.f,0.f,0.f};
    const bool doTW  = (cg == 0);
    const bool doCNT = doTW && ((bm & 3) == 0);

    if (tid == 0) { ISSUE(0, 0); ISSUE(1, 1); }

    // register prefetch of w/t for stage 0
    float4 wb = *(const float4*)(wsrc);
    int4 ta = {0,0,0,0}, tb2 = {0,0,0,0};
    if (is64) { ta = t64[0]; tb2 = t64[1]; }
    else      { ta = t32[0]; }

#pragma unroll 1
    for (int s = 0; s < NST; s++) {
        // ---- producer: issue stage j = s+2 into slot j%3 ----
        const int j = s + 2;
        if (tid == 0 && j < NST) {
            const int jslot = j % NSTAGE;
            if (j >= NSTAGE) mb_wait_rlx(EMPTYB(jslot), ((j / NSTAGE) - 1) & 1);
            ISSUE(j, jslot);
        }
        // ---- prefetch next stage's w/t into regs (overlaps the TMA wait) ----
        float4 wn = {0.f,0.f,0.f,0.f};
        int4 tna = {0,0,0,0}, tnb = {0,0,0,0};
        if (s + 1 < NST) {
            wn = *(const float4*)(wsrc + (s+1)*SELEM);
            if (is64) { tna = t64[(s+1)*1024]; tnb = t64[(s+1)*1024 + 1]; }
            else      { tna = t32[(s+1)*512]; }
        }

        // ---- consumer: wait for stage s (slot s%3, phase (s/3)&1) ----
        const int cslot = s % NSTAGE;
        mb_wait_acq(FULLB(cslot), (s / NSTAGE) & 1);
        const char* sb = dynsm + cslot*STAGE_B;

        int t0, t1, t2, t3;
        if (is64) { t0 = ta.x; t1 = ta.z; t2 = tb2.x; t3 = tb2.z; }
        else      { t0 = ta.x; t1 = ta.y; t2 = ta.z;  t3 = ta.w; }
        const int   ts[4] = { t0, t1, t2, t3 };
        const float ws[4] = { wb.x, wb.y, wb.z, wb.w };
        float msk[4][KK];
#pragma unroll
        for (int jj = 0; jj < 4; jj++)
#pragma unroll
            for (int k = 0; k < KK; k++)
                msk[jj][k] = (ts[jj] == k) ? ws[jj] : 0.f;

        if (doTW) {
#pragma unroll
            for (int k = 0; k < KK; k++)
                twl[k] += (msk[0][k] + msk[1][k]) + (msk[2][k] + msk[3][k]);
        }
        if (doCNT) {
#pragma unroll
            for (int k = 0; k < KK; k++) {
                float c0 = (t0==k)?1.f:0.f, c1 = (t1==k)?1.f:0.f;
                float c2 = (t2==k)?1.f:0.f, c3 = (t3==k)?1.f:0.f;
                cl[k] += (c0+c1)+(c2+c3);
            }
        }
#pragma unroll
        for (int cc = 0; cc < CB; cc++) {
            float4 fv = *(const float4*)(sb + cc*8192 + tid*16);
            const float fs[4] = { fv.x, fv.y, fv.z, fv.w };
#pragma unroll
            for (int k = 0; k < KK; k++) {
                acc[cc][k] += fs[0]*msk[0][k];
                acc[cc][k] += fs[1]*msk[1][k];
                acc[cc][k] += fs[2]*msk[2][k];
                acc[cc][k] += fs[3]*msk[3][k];
            }
        }
        if (lane == 0) MB_ARRIVE(EMPTYB(cslot));

        wb = wn; ta = tna; tb2 = tnb;
    }

    // ---- block-reduce 32 accumulators over 16 warps ----
#pragma unroll
    for (int cc = 0; cc < CB; cc++)
#pragma unroll
        for (int k = 0; k < KK; k++)
#pragma unroll
            for (int off = 16; off > 0; off >>= 1)
                acc[cc][k] += __shfl_down_sync(0xffffffffu, acc[cc][k], off);
    if (lane == 0) {
#pragma unroll
        for (int cc = 0; cc < CB; cc++)
#pragma unroll
            for (int k = 0; k < KK; k++) sred[wid][cc*KK + k] = acc[cc][k];
    }
    __syncthreads();
    const int bid = (bm*CG + cg)*VS + vs;
    if (tid < 32) {
        float s = 0.f;
#pragma unroll
        for (int ww = 0; ww < NWARP; ww++) s += sred[ww][tid];
        g_numpart[bid*32 + tid] = s;
    }
    __syncthreads();

    // ---- block-reduce tw/cnt ----
    {
        float vals[8];
#pragma unroll
        for (int jv = 0; jv < 4; jv++) { vals[jv] = twl[jv]; vals[4+jv] = cl[jv]; }
#pragma unroll
        for (int jv = 0; jv < 8; jv++)
#pragma unroll
            for (int off = 16; off > 0; off >>= 1)
                vals[jv] += __shfl_down_sync(0xffffffffu, vals[jv], off);
        if (lane == 0) {
#pragma unroll
            for (int jv = 0; jv < 8; jv++) sred[wid][jv] = vals[jv];
        }
        __syncthreads();
        if (tid < 8) {
            float s = 0.f;
#pragma unroll
            for (int ww = 0; ww < NWARP; ww++) s += sred[ww][tid];
            if (tid < 4) {
                if (doTW) g_twpart[(bm*VS + vs)*4 + tid] = s;
            } else {
                if (doCNT) g_cntpart[(b*VS + vs)*4 + (tid-4)] = s;
            }
        }
    }

    // ---- last-block-done finalize ----
    __threadfence();
    __syncthreads();
    if (tid == 0) {
        unsigned old = atomicAdd(&g_ctr, 1u);
        s_last = (old == (unsigned)(NBLK - 1));
    }
    __syncthreads();
    if (!s_last) return;

    // Phase A: tw (32) + cnt (8)
    if (tid < 32) {
        int bm_ = tid >> 2, k = tid & 3;
        float s = 0.f;
        for (int v = 0; v < VS; v++) s += g_twpart[(bm_*VS + v)*4 + k];
        s_tw[tid] = s + EPSL;
    } else if (tid < 40) {
        int jv = tid - 32, b_ = jv >> 2, k = jv & 3;
        float s = 0.f;
        for (int v = 0; v < VS; v++) s += g_cntpart[(b_*VS + v)*4 + k];
        s_cnt[jv] = s;
    }
    __syncthreads();

    // Phase B: proto raw = num / tw
    for (int cell = tid; cell < 2048; cell += THREADS) {
        int bm_ = cell >> 8;
        int rem = cell & 255;
        int c = rem >> 2, k = rem & 3;
        int cg_ = c >> 3, cc = c & 7;
        float s = 0.f;
        for (int v = 0; v < VS; v++)
            s += g_numpart[((bm_*CG + cg_)*VS + v)*32 + cc*4 + k];
        s_proto[(bm_*4 + k)*64 + c] = s / s_tw[bm_*4 + k];
    }
    __syncthreads();

    // Phase C: normalize 32 rows (16 warps x 2 rows)
#pragma unroll
    for (int jv = 0; jv < 2; jv++) {
        int r = wid + NWARP*jv;
        float v1 = s_proto[r*64 + lane];
        float v2 = s_proto[r*64 + lane + 32];
        float ss = v1*v1 + v2*v2;
#pragma unroll
        for (int off = 16; off > 0; off >>= 1)
            ss += __shfl_xor_sync(0xffffffffu, ss, off);
        float norm = fmaxf(sqrtf(fmaxf(ss, 1e-24f)), 1e-12f);
        float inv = 1.f / norm;
        s_proto[r*64 + lane]      = v1 * inv;
        s_proto[r*64 + lane + 32] = v2 * inv;
    }
    __syncthreads();

    // Phase D: 96 pair dot products (16 warps x 6 pairs)
    {
        const int p1t[6] = {0,0,0,1,1,2};
        const int p2t[6] = {1,2,3,2,3,3};
        for (int p = wid; p < 96; p += NWARP) {
            int r1, r2, outidx;
            bool val;
            bool isAlign = (p < 48);
            float om = 1.f;
            if (isAlign) {
                int pa = p;
                int b_ = pa / 24; int rem = pa % 24;
                int mp = rem >> 2, k = rem & 3;
                int m = p1t[mp], n = p2t[mp];
                r1 = (b_*4 + m)*4 + k;
                r2 = (b_*4 + n)*4 + k;
                val = (s_cnt[b_*4 + k] >= 1.f) && (k != 0);
                float cd = s_cnt[b_*4 + k] + EPSL;
                om = (s_tw[r1] / cd) * (s_tw[r2] / cd);
                outidx = pa;
            } else {
                int ps = p - 48;
                int b_ = ps / 24; int rem = ps % 24;
                int m = rem / 6, kp = rem % 6;
                int k1 = p1t[kp], k2 = p2t[kp];
                r1 = (b_*4 + m)*4 + k1;
                r2 = (b_*4 + m)*4 + k2;
                val = (s_cnt[b_*4 + k1] >= 1.f) && (k1 != 0) &&
                      (s_cnt[b_*4 + k2] >= 1.f) && (k2 != 0);
                outidx = ps;
            }
            float a1 = s_proto[r1*64 + lane],      b1 = s_proto[r2*64 + lane];
            float a2 = s_proto[r1*64 + lane + 32], b2 = s_proto[r2*64 + lane + 32];
            float dot = a1*b1 + a2*b2;
#pragma unroll
            for (int off = 16; off > 0; off >>= 1)
                dot += __shfl_xor_sync(0xffffffffu, dot, off);
            if (lane == 0) {
                if (isAlign) {
                    s_aterm[outidx] = val ? om * fmaxf(0.9f - dot, 0.f) : 0.f;
                    s_acnt[outidx]  = val ? 1.f : 0.f;
                } else {
                    s_sterm[outidx] = val ? fmaxf(dot - 0.1f, 0.f) : 0.f;
                    s_scnt[outidx]  = val ? 1.f : 0.f;
                }
            }
        }
    }
    __syncthreads();

    // Phase E: scalar loss + counter reset
    if (tid == 0) {
        float as = 0.f, ac = 0.f, ssum = 0.f, sc = 0.f;
        for (int i = 0; i < 48; i++) { as += s_aterm[i]; ac += s_acnt[i]; }
        for (int i = 0; i < 48; i++) { ssum += s_sterm[i]; sc += s_scnt[i]; }
        out[0] = as / (ac + EPSL) + ssum / (sc + EPSL);
        g_ctr = 0;
    }
}

extern "C" void kernel_launch(void* const* d_in, const int* in_sizes, int n_in,
                              void* d_out, int out_size) {
    const float* feats   = (const float*)d_in[0];
    const float* weights = (const float*)d_in[1];
    const int*   tgt_w   = (const int*)d_in[2];   // int32 or int64; detected on-device
    float* out = (float*)d_out;

    cudaFuncSetAttribute(kmain, cudaFuncAttributeMaxDynamicSharedMemorySize, DYN_BYTES);
    kmain<<<dim3(BB*MM, CG, VS), THREADS, DYN_BYTES>>>(feats, weights, tgt_w, out);
}